// round 10
// baseline (speedup 1.0000x reference)
#include <cuda_runtime.h>
#include <math.h>
#include <stdint.h>

#define BB 32
#define SS 4096
#define HH 1024
#define ROWS (BB * SS)        // 131072

// Scratch (no allocations allowed)
__device__ float    g_h[ROWS];
__device__ unsigned g_minkey[BB];   // ordered-uint encoded masked min of h
__device__ unsigned g_maxkey[BB];
__device__ int      g_mflag;        // 0 = uint8 mask, 1 = int32, 2 = float32

// Ordered-uint encoding: monotone map float -> uint32 (for atomicMin/Max)
__device__ __forceinline__ unsigned okey(float f)
{
    unsigned u = __float_as_uint(f);
    return (u & 0x80000000u) ? ~u : (u | 0x80000000u);
}
__device__ __forceinline__ float odec(unsigned k)
{
    unsigned u = (k & 0x80000000u) ? (k ^ 0x80000000u) : ~k;
    return __uint_as_float(u);
}

__device__ __forceinline__ bool mask_at(const void* m, int i, int flag)
{
    if (flag == 0) return reinterpret_cast<const uint8_t*>(m)[i] != 0;
    if (flag == 1) return reinterpret_cast<const int*>(m)[i] != 0;
    return reinterpret_cast<const float*>(m)[i] != 0.0f;
}

// ---------------------------------------------------------------------------
// Kernel 0: detect mask dtype (mask[:, :2] forced True by reference, so
// element 1 is truthy) + init min/max atomic keys. One warp.
// ---------------------------------------------------------------------------
__global__ void detect_kernel(const uint8_t* __restrict__ m)
{
    const int t = threadIdx.x;
    if (t == 0) {
        if (m[1] == 1) {
            g_mflag = 0;
        } else {
            int v = reinterpret_cast<const int*>(m)[1];
            g_mflag = (v == 1) ? 1 : 2;
        }
    }
    if (t < BB) {
        g_minkey[t] = 0xFFFFFFFFu;   // identity for min over keys
        g_maxkey[t] = 0u;            // identity for max over keys
    }
}

// ---------------------------------------------------------------------------
// Kernel 1: h[row] = dot(x[row,:], W) + bias, TWO rows per warp.
// W register-cached (8 float4/lane, reused across both rows); 16 independent
// streaming x loads in flight (__ldcs: evict-first, keep W resident in L1).
// Masked min/max folded in via ordered-uint atomics (hidden under DRAM time).
// ---------------------------------------------------------------------------
__global__ __launch_bounds__(256) void proj_kernel(
    const float* __restrict__ x,
    const float* __restrict__ W,
    const float* __restrict__ bias,
    const void*  __restrict__ mask)
{
    const int warp = (blockIdx.x * blockDim.x + threadIdx.x) >> 5;
    const int lane = threadIdx.x & 31;
    const int row0 = warp * 2;

    const float4* __restrict__ x0 = reinterpret_cast<const float4*>(x) + (size_t)row0 * (HH / 4);
    const float4* __restrict__ x1 = x0 + (HH / 4);
    const float4* __restrict__ Wv = reinterpret_cast<const float4*>(W);

    float4 w[8];
#pragma unroll
    for (int k = 0; k < 8; k++)
        w[k] = __ldg(&Wv[k * 32 + lane]);

    float a0 = 0.0f, a1 = 0.0f;
#pragma unroll
    for (int k = 0; k < 8; k++) {
        float4 v0 = __ldcs(&x0[k * 32 + lane]);
        float4 v1 = __ldcs(&x1[k * 32 + lane]);
        a0 = fmaf(v0.x, w[k].x, a0);
        a0 = fmaf(v0.y, w[k].y, a0);
        a0 = fmaf(v0.z, w[k].z, a0);
        a0 = fmaf(v0.w, w[k].w, a0);
        a1 = fmaf(v1.x, w[k].x, a1);
        a1 = fmaf(v1.y, w[k].y, a1);
        a1 = fmaf(v1.z, w[k].z, a1);
        a1 = fmaf(v1.w, w[k].w, a1);
    }
#pragma unroll
    for (int o = 16; o; o >>= 1) {
        a0 += __shfl_xor_sync(0xffffffffu, a0, o);
        a1 += __shfl_xor_sync(0xffffffffu, a1, o);
    }

    if (lane == 0) {
        const float bb = bias[0];
        const float h0 = a0 + bb;
        const float h1 = a1 + bb;
        g_h[row0]     = h0;
        g_h[row0 + 1] = h1;

        const int flag = g_mflag;
        const int b = row0 >> 12;            // both rows in same b (pair-aligned)
        if (mask_at(mask, row0, flag)) {
            unsigned k0 = okey(h0);
            atomicMin(&g_minkey[b], k0);
            atomicMax(&g_maxkey[b], k0);
        }
        if (mask_at(mask, row0 + 1, flag)) {
            unsigned k1 = okey(h1);
            atomicMin(&g_minkey[b], k1);
            atomicMax(&g_maxkey[b], k1);
        }
    }
}

// ---------------------------------------------------------------------------
// Kernel 2: out[i] = mask[i] ? (h[i]-mn)/(mx-mn) : 0, 4 elements per thread.
// (Reference's mean/std cancel exactly: (z-zmin)/(zmax-zmin) ==
//  (h-hmin)/(hmax-hmin) over the mask.)
// ---------------------------------------------------------------------------
__global__ __launch_bounds__(256) void finalize_kernel(
    const void* __restrict__ mask,
    float* __restrict__ out)
{
    const int g  = blockIdx.x * 256 + threadIdx.x;   // group of 4 elements
    const int i  = g * 4;
    const int b  = i >> 12;

    const float mn  = odec(g_minkey[b]);
    const float mx  = odec(g_maxkey[b]);
    const float inv = 1.0f / (mx - mn);
    const int flag  = g_mflag;

    float4 h = reinterpret_cast<const float4*>(g_h)[g];

    bool m0, m1, m2, m3;
    if (flag == 0) {
        uchar4 mc = reinterpret_cast<const uchar4*>(mask)[g];
        m0 = mc.x; m1 = mc.y; m2 = mc.z; m3 = mc.w;
    } else if (flag == 1) {
        int4 mi = reinterpret_cast<const int4*>(mask)[g];
        m0 = mi.x; m1 = mi.y; m2 = mi.z; m3 = mi.w;
    } else {
        float4 mf = reinterpret_cast<const float4*>(mask)[g];
        m0 = mf.x != 0.0f; m1 = mf.y != 0.0f; m2 = mf.z != 0.0f; m3 = mf.w != 0.0f;
    }

    float4 o;
    o.x = m0 ? (h.x - mn) * inv : 0.0f;
    o.y = m1 ? (h.y - mn) * inv : 0.0f;
    o.z = m2 ? (h.z - mn) * inv : 0.0f;
    o.w = m3 ? (h.w - mn) * inv : 0.0f;
    reinterpret_cast<float4*>(out)[g] = o;
}

// ---------------------------------------------------------------------------
extern "C" void kernel_launch(void* const* d_in, const int* in_sizes, int n_in,
                              void* d_out, int out_size)
{
    // Bind inputs by element count (all four are distinct):
    //   input = 33554432, mask = 131072, W = 1024, b = 1
    const float* x    = nullptr;
    const void*  mask = nullptr;
    const float* W    = nullptr;
    const float* bias = nullptr;
    for (int i = 0; i < n_in; i++) {
        if      (in_sizes[i] == BB * SS * HH) x    = (const float*)d_in[i];
        else if (in_sizes[i] == BB * SS)      mask = d_in[i];
        else if (in_sizes[i] == HH)           W    = (const float*)d_in[i];
        else if (in_sizes[i] == 1)            bias = (const float*)d_in[i];
    }
    float* out = (float*)d_out;
    (void)out_size;

    detect_kernel<<<1, 32>>>((const uint8_t*)mask);
    proj_kernel<<<ROWS / 16, 256>>>(x, W, bias, mask);   // 2 rows/warp, 8 warps/block
    finalize_kernel<<<ROWS / 4 / 256, 256>>>(mask, out); // 4 elems/thread
}

// round 12
// speedup vs baseline: 1.3713x; 1.3713x over previous
#include <cuda_runtime.h>
#include <math.h>
#include <stdint.h>

#define BB 32
#define SS 4096
#define HH 1024
#define ROWS (BB * SS)        // 131072

// Scratch (no allocations allowed)
__device__ float g_h[ROWS];
__device__ float g_min[BB];
__device__ float g_max[BB];

// ---------------------------------------------------------------------------
// Mask dtype is detected inline per kernel (no extra launch): the reference
// forces mask[:, :2] = True, so element 1 is truthy.
//   uint8  : byte[1] == 1
//   int32  : word[1] == 1          (byte[1] == 0)
//   float32: word[1] == 0x3F800000 (byte[1] == 0)
// Both probe loads are warp-uniform L2/L1 hits — effectively free.
// ---------------------------------------------------------------------------
__device__ __forceinline__ int mask_flag(const void* m)
{
    if (reinterpret_cast<const uint8_t*>(m)[1] == 1) return 0;
    return (reinterpret_cast<const int*>(m)[1] == 1) ? 1 : 2;
}

__device__ __forceinline__ bool mask_at(const void* m, int i, int flag)
{
    if (flag == 0) return reinterpret_cast<const uint8_t*>(m)[i] != 0;
    if (flag == 1) return reinterpret_cast<const int*>(m)[i] != 0;
    return reinterpret_cast<const float*>(m)[i] != 0.0f;
}

// ---------------------------------------------------------------------------
// Kernel 1 (R6-verified form, ~87us = ~6.2 TB/s): h[row] = dot(x[row,:], W)+b.
// One warp per row; 8 x float4 coalesced loads per lane; W L1-resident.
// ---------------------------------------------------------------------------
__global__ __launch_bounds__(256) void proj_kernel(
    const float* __restrict__ x,
    const float* __restrict__ W,
    const float* __restrict__ bias)
{
    const int warp = (blockIdx.x * blockDim.x + threadIdx.x) >> 5;
    const int lane = threadIdx.x & 31;

    const float4* __restrict__ xr = reinterpret_cast<const float4*>(x) + (size_t)warp * (HH / 4);
    const float4* __restrict__ Wv = reinterpret_cast<const float4*>(W);

    float acc = 0.0f;
#pragma unroll
    for (int k = 0; k < HH / 128; k++) {       // 8 iterations
        float4 xv = xr[k * 32 + lane];
        float4 wv = Wv[k * 32 + lane];
        acc = fmaf(xv.x, wv.x, acc);
        acc = fmaf(xv.y, wv.y, acc);
        acc = fmaf(xv.z, wv.z, acc);
        acc = fmaf(xv.w, wv.w, acc);
    }
#pragma unroll
    for (int o = 16; o; o >>= 1)
        acc += __shfl_xor_sync(0xffffffffu, acc, o);

    if (lane == 0)
        g_h[warp] = acc + bias[0];
}

// ---------------------------------------------------------------------------
// Kernel 2: per-b masked min/max of h over S. One block per b, 16 elem/thread,
// float4 h loads.
// ---------------------------------------------------------------------------
__global__ __launch_bounds__(256) void minmax_kernel(const void* __restrict__ mask)
{
    const int b   = blockIdx.x;
    const int tid = threadIdx.x;
    const int flag = mask_flag(mask);
    const float4* __restrict__ h4 = reinterpret_cast<const float4*>(g_h + (size_t)b * SS);

    float mn = INFINITY, mx = -INFINITY;
#pragma unroll
    for (int it = 0; it < 4; it++) {           // 4 * 256 float4 groups = 4096 elems
        const int g = it * 256 + tid;          // group index within row
        float4 h = h4[g];
        const int base = b * SS + g * 4;
        if (mask_at(mask, base + 0, flag)) { mn = fminf(mn, h.x); mx = fmaxf(mx, h.x); }
        if (mask_at(mask, base + 1, flag)) { mn = fminf(mn, h.y); mx = fmaxf(mx, h.y); }
        if (mask_at(mask, base + 2, flag)) { mn = fminf(mn, h.z); mx = fmaxf(mx, h.z); }
        if (mask_at(mask, base + 3, flag)) { mn = fminf(mn, h.w); mx = fmaxf(mx, h.w); }
    }
#pragma unroll
    for (int o = 16; o; o >>= 1) {
        mn = fminf(mn, __shfl_xor_sync(0xffffffffu, mn, o));
        mx = fmaxf(mx, __shfl_xor_sync(0xffffffffu, mx, o));
    }

    __shared__ float smn[8], smx[8];
    const int wid = tid >> 5;
    if ((tid & 31) == 0) { smn[wid] = mn; smx[wid] = mx; }
    __syncthreads();

    if (wid == 0) {
        const int lane = tid & 31;
        mn = (lane < 8) ? smn[lane] : INFINITY;
        mx = (lane < 8) ? smx[lane] : -INFINITY;
#pragma unroll
        for (int o = 4; o; o >>= 1) {
            mn = fminf(mn, __shfl_xor_sync(0xffffffffu, mn, o));
            mx = fmaxf(mx, __shfl_xor_sync(0xffffffffu, mx, o));
        }
        if (lane == 0) { g_min[b] = mn; g_max[b] = mx; }
    }
}

// ---------------------------------------------------------------------------
// Kernel 3: out[i] = mask[i] ? (h[i]-mn)/(mx-mn) : 0, 4 elements per thread.
// (Reference's mean/std cancel exactly: (z-zmin)/(zmax-zmin) ==
//  (h-hmin)/(hmax-hmin) over the mask; the +EPS on std also cancels.)
// ---------------------------------------------------------------------------
__global__ __launch_bounds__(256) void finalize_kernel(
    const void* __restrict__ mask,
    float* __restrict__ out)
{
    const int g = blockIdx.x * 256 + threadIdx.x;    // group of 4 elements
    const int i = g * 4;
    const int b = i >> 12;

    const float mn  = g_min[b];
    const float inv = 1.0f / (g_max[b] - mn);
    const int flag  = mask_flag(mask);

    float4 h = reinterpret_cast<const float4*>(g_h)[g];

    bool m0, m1, m2, m3;
    if (flag == 0) {
        uchar4 mc = reinterpret_cast<const uchar4*>(mask)[g];
        m0 = mc.x; m1 = mc.y; m2 = mc.z; m3 = mc.w;
    } else if (flag == 1) {
        int4 mi = reinterpret_cast<const int4*>(mask)[g];
        m0 = mi.x; m1 = mi.y; m2 = mi.z; m3 = mi.w;
    } else {
        float4 mf = reinterpret_cast<const float4*>(mask)[g];
        m0 = mf.x != 0.0f; m1 = mf.y != 0.0f; m2 = mf.z != 0.0f; m3 = mf.w != 0.0f;
    }

    float4 o;
    o.x = m0 ? (h.x - mn) * inv : 0.0f;
    o.y = m1 ? (h.y - mn) * inv : 0.0f;
    o.z = m2 ? (h.z - mn) * inv : 0.0f;
    o.w = m3 ? (h.w - mn) * inv : 0.0f;
    reinterpret_cast<float4*>(out)[g] = o;
}

// ---------------------------------------------------------------------------
extern "C" void kernel_launch(void* const* d_in, const int* in_sizes, int n_in,
                              void* d_out, int out_size)
{
    // Bind inputs by element count (all four are distinct):
    //   input = 33554432, mask = 131072, W = 1024, b = 1
    const float* x    = nullptr;
    const void*  mask = nullptr;
    const float* W    = nullptr;
    const float* bias = nullptr;
    for (int i = 0; i < n_in; i++) {
        if      (in_sizes[i] == BB * SS * HH) x    = (const float*)d_in[i];
        else if (in_sizes[i] == BB * SS)      mask = d_in[i];
        else if (in_sizes[i] == HH)           W    = (const float*)d_in[i];
        else if (in_sizes[i] == 1)            bias = (const float*)d_in[i];
    }
    float* out = (float*)d_out;
    (void)out_size;

    proj_kernel<<<ROWS / 8, 256>>>(x, W, bias);          // 1 warp per row (R6-verified)
    minmax_kernel<<<BB, 256>>>(mask);
    finalize_kernel<<<ROWS / 4 / 256, 256>>>(mask, out); // 4 elems/thread
}

// round 13
// speedup vs baseline: 1.3920x; 1.0151x over previous
#include <cuda_runtime.h>
#include <math.h>
#include <stdint.h>

#define BB 32
#define SS 4096
#define HH 1024
#define ROWS (BB * SS)        // 131072

// Scratch (no allocations allowed)
__device__ float g_h[ROWS];

// ---------------------------------------------------------------------------
// Mask dtype detected inline (reference forces mask[:, :2] = True, so element
// 1 is truthy):
//   uint8  : byte[1] == 1
//   int32  : word[1] == 1          (byte[1] == 0)
//   float32: word[1] == 0x3F800000 (byte[1] == 0)
// Probe loads are warp-uniform L1/L2 hits — effectively free.
// ---------------------------------------------------------------------------
__device__ __forceinline__ int mask_flag(const void* m)
{
    if (reinterpret_cast<const uint8_t*>(m)[1] == 1) return 0;
    return (reinterpret_cast<const int*>(m)[1] == 1) ? 1 : 2;
}

// ---------------------------------------------------------------------------
// Kernel 1 (verified, 77.7us @ 87.8% DRAM): h[row] = dot(x[row,:], W) + b.
// One warp per row; 8 x float4 coalesced loads per lane; W L1-resident.
// ---------------------------------------------------------------------------
__global__ __launch_bounds__(256) void proj_kernel(
    const float* __restrict__ x,
    const float* __restrict__ W,
    const float* __restrict__ bias)
{
    const int warp = (blockIdx.x * blockDim.x + threadIdx.x) >> 5;
    const int lane = threadIdx.x & 31;

    const float4* __restrict__ xr = reinterpret_cast<const float4*>(x) + (size_t)warp * (HH / 4);
    const float4* __restrict__ Wv = reinterpret_cast<const float4*>(W);

    float acc = 0.0f;
#pragma unroll
    for (int k = 0; k < HH / 128; k++) {       // 8 iterations
        float4 xv = xr[k * 32 + lane];
        float4 wv = Wv[k * 32 + lane];
        acc = fmaf(xv.x, wv.x, acc);
        acc = fmaf(xv.y, wv.y, acc);
        acc = fmaf(xv.z, wv.z, acc);
        acc = fmaf(xv.w, wv.w, acc);
    }
#pragma unroll
    for (int o = 16; o; o >>= 1)
        acc += __shfl_xor_sync(0xffffffffu, acc, o);

    if (lane == 0)
        g_h[warp] = acc + bias[0];
}

// ---------------------------------------------------------------------------
// Kernel 2 (fused tail): one block per b. Each thread owns 4 consecutive
// elements: load h (float4) + mask once, block-reduce masked min/max, then
// write outputs from the SAME registers. Removes the separate finalize launch,
// the h/mask re-read, and the g_min/g_max global round-trip.
// (Reference's mean/std cancel exactly: (z-zmin)/(zmax-zmin) ==
//  (h-hmin)/(hmax-hmin) over the mask; the +EPS on std cancels too.)
// ---------------------------------------------------------------------------
__global__ __launch_bounds__(1024) void tail_kernel(
    const void* __restrict__ mask,
    float* __restrict__ out)
{
    const int b   = blockIdx.x;
    const int tid = threadIdx.x;
    const int g   = b * (SS / 4) + tid;        // global float4-group index
    const int flag = mask_flag(mask);

    // Load this thread's 4 h values and mask bits once.
    float4 h = reinterpret_cast<const float4*>(g_h)[g];

    bool m0, m1, m2, m3;
    if (flag == 0) {
        uchar4 mc = reinterpret_cast<const uchar4*>(mask)[g];
        m0 = mc.x; m1 = mc.y; m2 = mc.z; m3 = mc.w;
    } else if (flag == 1) {
        int4 mi = reinterpret_cast<const int4*>(mask)[g];
        m0 = mi.x; m1 = mi.y; m2 = mi.z; m3 = mi.w;
    } else {
        float4 mf = reinterpret_cast<const float4*>(mask)[g];
        m0 = mf.x != 0.0f; m1 = mf.y != 0.0f; m2 = mf.z != 0.0f; m3 = mf.w != 0.0f;
    }

    // Masked min/max over this thread's 4 elements.
    float mn = INFINITY, mx = -INFINITY;
    if (m0) { mn = fminf(mn, h.x); mx = fmaxf(mx, h.x); }
    if (m1) { mn = fminf(mn, h.y); mx = fmaxf(mx, h.y); }
    if (m2) { mn = fminf(mn, h.z); mx = fmaxf(mx, h.z); }
    if (m3) { mn = fminf(mn, h.w); mx = fmaxf(mx, h.w); }

    // Warp reduce.
#pragma unroll
    for (int o = 16; o; o >>= 1) {
        mn = fminf(mn, __shfl_xor_sync(0xffffffffu, mn, o));
        mx = fmaxf(mx, __shfl_xor_sync(0xffffffffu, mx, o));
    }

    // Block reduce across 32 warps.
    __shared__ float smn[32], smx[32];
    __shared__ float bmn, binv;
    const int wid = tid >> 5;
    const int lane = tid & 31;
    if (lane == 0) { smn[wid] = mn; smx[wid] = mx; }
    __syncthreads();

    if (wid == 0) {
        mn = smn[lane];
        mx = smx[lane];
#pragma unroll
        for (int o = 16; o; o >>= 1) {
            mn = fminf(mn, __shfl_xor_sync(0xffffffffu, mn, o));
            mx = fmaxf(mx, __shfl_xor_sync(0xffffffffu, mx, o));
        }
        if (lane == 0) { bmn = mn; binv = 1.0f / (mx - mn); }
    }
    __syncthreads();

    const float fmn  = bmn;
    const float finv = binv;

    float4 o;
    o.x = m0 ? (h.x - fmn) * finv : 0.0f;
    o.y = m1 ? (h.y - fmn) * finv : 0.0f;
    o.z = m2 ? (h.z - fmn) * finv : 0.0f;
    o.w = m3 ? (h.w - fmn) * finv : 0.0f;
    reinterpret_cast<float4*>(out)[g] = o;
}

// ---------------------------------------------------------------------------
extern "C" void kernel_launch(void* const* d_in, const int* in_sizes, int n_in,
                              void* d_out, int out_size)
{
    // Bind inputs by element count (all four are distinct):
    //   input = 33554432, mask = 131072, W = 1024, b = 1
    const float* x    = nullptr;
    const void*  mask = nullptr;
    const float* W    = nullptr;
    const float* bias = nullptr;
    for (int i = 0; i < n_in; i++) {
        if      (in_sizes[i] == BB * SS * HH) x    = (const float*)d_in[i];
        else if (in_sizes[i] == BB * SS)      mask = d_in[i];
        else if (in_sizes[i] == HH)           W    = (const float*)d_in[i];
        else if (in_sizes[i] == 1)            bias = (const float*)d_in[i];
    }
    float* out = (float*)d_out;
    (void)out_size;

    proj_kernel<<<ROWS / 8, 256>>>(x, W, bias);   // 1 warp per row (verified)
    tail_kernel<<<BB, 1024>>>(mask, out);         // fused minmax + finalize
}

// round 14
// speedup vs baseline: 1.3974x; 1.0039x over previous
#include <cuda_runtime.h>
#include <math.h>
#include <stdint.h>

#define BB 32
#define SS 4096
#define HH 1024
#define ROWS (BB * SS)        // 131072

// Scratch (statically initialized; finalize restores these values each call,
// so every graph replay sees identity keys — no init kernel needed)
__device__ float    g_h[ROWS];
__device__ unsigned g_minkey[BB] = {
    0xFFFFFFFFu,0xFFFFFFFFu,0xFFFFFFFFu,0xFFFFFFFFu,0xFFFFFFFFu,0xFFFFFFFFu,0xFFFFFFFFu,0xFFFFFFFFu,
    0xFFFFFFFFu,0xFFFFFFFFu,0xFFFFFFFFu,0xFFFFFFFFu,0xFFFFFFFFu,0xFFFFFFFFu,0xFFFFFFFFu,0xFFFFFFFFu,
    0xFFFFFFFFu,0xFFFFFFFFu,0xFFFFFFFFu,0xFFFFFFFFu,0xFFFFFFFFu,0xFFFFFFFFu,0xFFFFFFFFu,0xFFFFFFFFu,
    0xFFFFFFFFu,0xFFFFFFFFu,0xFFFFFFFFu,0xFFFFFFFFu,0xFFFFFFFFu,0xFFFFFFFFu,0xFFFFFFFFu,0xFFFFFFFFu};
__device__ unsigned g_maxkey[BB] = {0};   // zero = identity for max over keys
__device__ int      g_done[BB]   = {0};

// Ordered-uint encoding: monotone float -> uint32 (atomicMin/Max compatible)
__device__ __forceinline__ unsigned okey(float f)
{
    unsigned u = __float_as_uint(f);
    return (u & 0x80000000u) ? ~u : (u | 0x80000000u);
}
__device__ __forceinline__ float odec(unsigned k)
{
    unsigned u = (k & 0x80000000u) ? (k ^ 0x80000000u) : ~k;
    return __uint_as_float(u);
}

// Mask dtype detected inline (reference forces mask[:, :2]=True, so element 1
// is truthy): uint8 -> byte[1]==1; int32 -> word[1]==1; float32 -> word[1]==0x3F800000.
__device__ __forceinline__ int mask_flag(const void* m)
{
    if (reinterpret_cast<const uint8_t*>(m)[1] == 1) return 0;
    return (reinterpret_cast<const int*>(m)[1] == 1) ? 1 : 2;
}
__device__ __forceinline__ bool mask_at(const void* m, int i, int flag)
{
    if (flag == 0) return reinterpret_cast<const uint8_t*>(m)[i] != 0;
    if (flag == 1) return reinterpret_cast<const int*>(m)[i] != 0;
    return reinterpret_cast<const float*>(m)[i] != 0.0f;
}

// ---------------------------------------------------------------------------
// Kernel 1: h[row] = dot(x[row,:], W) + b (verified core, 77.7us @ 87.8% DRAM)
// + per-block masked min/max pre-reduce folded in: ONE atomic pair per block
// (16384 pairs, 512 per address, staggered over 77us — fully hidden).
// All 8 rows of a block share the same b (4096 % 8 == 0).
// ---------------------------------------------------------------------------
__global__ __launch_bounds__(256) void proj_kernel(
    const float* __restrict__ x,
    const float* __restrict__ W,
    const float* __restrict__ bias,
    const void*  __restrict__ mask)
{
    const int warp = (blockIdx.x * blockDim.x + threadIdx.x) >> 5;
    const int lane = threadIdx.x & 31;
    const int wid  = threadIdx.x >> 5;

    const float4* __restrict__ xr = reinterpret_cast<const float4*>(x) + (size_t)warp * (HH / 4);
    const float4* __restrict__ Wv = reinterpret_cast<const float4*>(W);

    float acc = 0.0f;
#pragma unroll
    for (int k = 0; k < HH / 128; k++) {       // 8 iterations
        float4 xv = xr[k * 32 + lane];
        float4 wv = Wv[k * 32 + lane];
        acc = fmaf(xv.x, wv.x, acc);
        acc = fmaf(xv.y, wv.y, acc);
        acc = fmaf(xv.z, wv.z, acc);
        acc = fmaf(xv.w, wv.w, acc);
    }
#pragma unroll
    for (int o = 16; o; o >>= 1)
        acc += __shfl_xor_sync(0xffffffffu, acc, o);

    __shared__ unsigned s_mnk[8], s_mxk[8];

    if (lane == 0) {
        const float h = acc + bias[0];
        g_h[warp] = h;
        const int flag = mask_flag(mask);
        const bool mv  = mask_at(mask, warp, flag);
        const unsigned k = okey(h);
        s_mnk[wid] = mv ? k : 0xFFFFFFFFu;
        s_mxk[wid] = mv ? k : 0u;
    }
    __syncthreads();

    if (threadIdx.x == 0) {
        unsigned mn = 0xFFFFFFFFu, mx = 0u;
#pragma unroll
        for (int i = 0; i < 8; i++) {
            mn = min(mn, s_mnk[i]);
            mx = max(mx, s_mxk[i]);
        }
        const int b = blockIdx.x >> 9;         // 512 blocks per b
        atomicMin(&g_minkey[b], mn);
        atomicMax(&g_maxkey[b], mx);
    }
}

// ---------------------------------------------------------------------------
// Kernel 2: reduction-free finalize, 128 blocks x 256 threads, 4 elems/thread.
// out[i] = mask[i] ? (h[i]-mn)/(mx-mn) : 0
// (Reference's mean/std cancel exactly: (z-zmin)/(zmax-zmin) ==
//  (h-hmin)/(hmax-hmin) over the mask; the +EPS on std cancels too.)
// Last of the 4 blocks per b resets the atomic keys for the next graph replay
// (stores -> __threadfence -> done-counter: no block can see a reset before
// all reads in all blocks of this b completed).
// ---------------------------------------------------------------------------
__global__ __launch_bounds__(256) void finalize_kernel(
    const void* __restrict__ mask,
    float* __restrict__ out)
{
    const int g = blockIdx.x * 256 + threadIdx.x;    // float4-group index
    const int b = blockIdx.x >> 2;                   // 4 blocks per b

    const float mn  = odec(g_minkey[b]);
    const float inv = 1.0f / (odec(g_maxkey[b]) - mn);
    const int flag  = mask_flag(mask);

    float4 h = reinterpret_cast<const float4*>(g_h)[g];

    bool m0, m1, m2, m3;
    if (flag == 0) {
        uchar4 mc = reinterpret_cast<const uchar4*>(mask)[g];
        m0 = mc.x; m1 = mc.y; m2 = mc.z; m3 = mc.w;
    } else if (flag == 1) {
        int4 mi = reinterpret_cast<const int4*>(mask)[g];
        m0 = mi.x; m1 = mi.y; m2 = mi.z; m3 = mi.w;
    } else {
        float4 mf = reinterpret_cast<const float4*>(mask)[g];
        m0 = mf.x != 0.0f; m1 = mf.y != 0.0f; m2 = mf.z != 0.0f; m3 = mf.w != 0.0f;
    }

    float4 o;
    o.x = m0 ? (h.x - mn) * inv : 0.0f;
    o.y = m1 ? (h.y - mn) * inv : 0.0f;
    o.z = m2 ? (h.z - mn) * inv : 0.0f;
    o.w = m3 ? (h.w - mn) * inv : 0.0f;
    reinterpret_cast<float4*>(out)[g] = o;

    // Reset protocol for next replay.
    __syncthreads();
    if (threadIdx.x == 0) {
        __threadfence();                              // order reads/stores above
        const int old = atomicAdd(&g_done[b], 1);
        if (old == 3) {                               // last block of this b
            g_minkey[b] = 0xFFFFFFFFu;
            g_maxkey[b] = 0u;
            g_done[b]   = 0;
        }
    }
}

// ---------------------------------------------------------------------------
extern "C" void kernel_launch(void* const* d_in, const int* in_sizes, int n_in,
                              void* d_out, int out_size)
{
    // Bind inputs by element count (all four are distinct):
    //   input = 33554432, mask = 131072, W = 1024, b = 1
    const float* x    = nullptr;
    const void*  mask = nullptr;
    const float* W    = nullptr;
    const float* bias = nullptr;
    for (int i = 0; i < n_in; i++) {
        if      (in_sizes[i] == BB * SS * HH) x    = (const float*)d_in[i];
        else if (in_sizes[i] == BB * SS)      mask = d_in[i];
        else if (in_sizes[i] == HH)           W    = (const float*)d_in[i];
        else if (in_sizes[i] == 1)            bias = (const float*)d_in[i];
    }
    float* out = (float*)d_out;
    (void)out_size;

    proj_kernel<<<ROWS / 8, 256>>>(x, W, bias, mask);     // 1 warp/row + minmax atomics
    finalize_kernel<<<ROWS / 4 / 256, 256>>>(mask, out);  // 128 blocks, no reduction
}